// round 1
// baseline (speedup 1.0000x reference)
#include <cuda_runtime.h>
#include <cuda_bf16.h>

#define F_IN  512
#define HID   16
#define C_OUT 40
#define MAXN  100000
#define MAXE  3200000

// ---------------- scratch (static device globals, no allocs) ----------------
__device__ __align__(128) int   g_deg [MAXN];
__device__ __align__(128) float g_dinv[MAXN];
__device__ __align__(128) float g_norm[MAXE];
__device__ __align__(128) float g_B1  [MAXN * HID];   // h, later a=relu(y1+b1)
__device__ __align__(128) float g_B2  [MAXN * HID];   // y1, later y2

// ---------------- helpers ----------------
__device__ __forceinline__ void red4(float4* p, float4 v) {
    asm volatile("red.global.add.v4.f32 [%0], {%1,%2,%3,%4};"
                 :: "l"(p), "f"(v.x), "f"(v.y), "f"(v.z), "f"(v.w)
                 : "memory");
}

// ---------------- kernels ----------------
__global__ void k_zero_deg(int* deg, int N) {
    int i = blockIdx.x * blockDim.x + threadIdx.x;
    if (i < N) deg[i] = 0;
}

__global__ void k_hist(const int* __restrict__ dst, int* deg, int E) {
    int i = blockIdx.x * blockDim.x + threadIdx.x;
    if (i < E) atomicAdd(&deg[dst[i]], 1);
}

__global__ void k_dinv(const int* __restrict__ deg, float* dinv, int N) {
    int i = blockIdx.x * blockDim.x + threadIdx.x;
    if (i < N) dinv[i] = rsqrtf((float)(deg[i] + 1));   // +1 = self-loop
}

__global__ void k_norm(const int* __restrict__ src, const int* __restrict__ dst,
                       const float* __restrict__ dinv, float* nrm, int E) {
    int i = blockIdx.x * blockDim.x + threadIdx.x;
    if (i < E) nrm[i] = dinv[src[i]] * dinv[dst[i]];
}

// GEMM1: h[N,16] = x[N,512] @ W1[512,16]
// 64 threads/block, 256 rows/block (4 rows/thread), k-tiles of 16 staged in smem.
#define G1_PR 257   // padded row stride for x tile (2-way STS conflicts, 0-way LDS)
__global__ __launch_bounds__(64) void k_gemm1(const float* __restrict__ x,
                                              const float* __restrict__ W1,
                                              float* __restrict__ h, int N) {
    __shared__ float sx[16 * G1_PR];  // [kk][r]  16 x 257
    __shared__ float wt[256];         // [kk][j]  16 x 16
    const int t    = threadIdx.x;
    const int base = blockIdx.x * 256;

    float acc[4][16];
#pragma unroll
    for (int m = 0; m < 4; m++)
#pragma unroll
        for (int j = 0; j < 16; j++) acc[m][j] = 0.f;

    for (int kt = 0; kt < F_IN / 16; kt++) {
        __syncthreads();
        // W1 tile: 256 floats
#pragma unroll
        for (int i = t; i < 256; i += 64) wt[i] = W1[kt * 256 + i];
        // x tile: 256 rows x 16 k = 1024 float4, 16 per thread
#pragma unroll
        for (int i = 0; i < 16; i++) {
            int c = t + 64 * i;
            int r = c >> 2, q = c & 3;
            int rg = base + r;
            float4 v = make_float4(0.f, 0.f, 0.f, 0.f);
            if (rg < N)
                v = *(const float4*)&x[(size_t)rg * F_IN + kt * 16 + q * 4];
            sx[(4 * q + 0) * G1_PR + r] = v.x;
            sx[(4 * q + 1) * G1_PR + r] = v.y;
            sx[(4 * q + 2) * G1_PR + r] = v.z;
            sx[(4 * q + 3) * G1_PR + r] = v.w;
        }
        __syncthreads();
#pragma unroll
        for (int kk = 0; kk < 16; kk++) {
            float x0 = sx[kk * G1_PR + t];
            float x1 = sx[kk * G1_PR + t + 64];
            float x2 = sx[kk * G1_PR + t + 128];
            float x3 = sx[kk * G1_PR + t + 192];
#pragma unroll
            for (int j = 0; j < 16; j++) {
                float w = wt[kk * 16 + j];
                acc[0][j] += x0 * w;
                acc[1][j] += x1 * w;
                acc[2][j] += x2 * w;
                acc[3][j] += x3 * w;
            }
        }
    }
#pragma unroll
    for (int m = 0; m < 4; m++) {
        int rg = base + t + 64 * m;
        if (rg < N) {
#pragma unroll
            for (int j4 = 0; j4 < 4; j4++) {
                float4 v = make_float4(acc[m][4 * j4 + 0], acc[m][4 * j4 + 1],
                                       acc[m][4 * j4 + 2], acc[m][4 * j4 + 3]);
                *(float4*)&h[(size_t)rg * HID + 4 * j4] = v;
            }
        }
    }
}

// out[i][:] = dinv[i]^2 * in[i][:]   (self-loop term; also initializes the buffer)
__global__ void k_selfinit(const float4* __restrict__ in4, const float* __restrict__ dinv,
                           float4* __restrict__ out4, int N) {
    int i = blockIdx.x * blockDim.x + threadIdx.x;
    if (i < N * (HID / 4)) {
        float dv = dinv[i >> 2];
        float s  = dv * dv;
        float4 v = in4[i];
        out4[i] = make_float4(v.x * s, v.y * s, v.z * s, v.w * s);
    }
}

// edge aggregation: out[dst] += norm * in[src], 4 threads per edge (float4 chunks)
__global__ void k_agg(const int* __restrict__ src, const int* __restrict__ dst,
                      const float* __restrict__ nrm, const float4* __restrict__ in4,
                      float4* out4, int E) {
    int tid = blockIdx.x * blockDim.x + threadIdx.x;
    int e = tid >> 2;
    int c = tid & 3;
    if (e < E) {
        int s = src[e];
        int d = dst[e];
        float n = nrm[e];
        float4 v = in4[s * 4 + c];
        red4(out4 + (size_t)d * 4 + c, make_float4(v.x * n, v.y * n, v.z * n, v.w * n));
    }
}

// a = relu(y1 + b1)
__global__ void k_relubias(const float4* __restrict__ in4, const float* __restrict__ b1,
                           float4* __restrict__ out4, int N) {
    int i = blockIdx.x * blockDim.x + threadIdx.x;
    if (i < N * (HID / 4)) {
        int jb = (i & 3) * 4;
        float4 v = in4[i];
        v.x = fmaxf(v.x + b1[jb + 0], 0.f);
        v.y = fmaxf(v.y + b1[jb + 1], 0.f);
        v.z = fmaxf(v.z + b1[jb + 2], 0.f);
        v.w = fmaxf(v.w + b1[jb + 3], 0.f);
        out4[i] = v;
    }
}

// GEMM2 + b2: out[N,40] = y2[N,16] @ W2[16,40] + b2
__global__ __launch_bounds__(128) void k_gemm2(const float* __restrict__ y2,
                                               const float* __restrict__ W2,
                                               const float* __restrict__ b2,
                                               float* __restrict__ out, int N) {
    __shared__ float w2s[HID * C_OUT];
    __shared__ float b2s[C_OUT];
    int t = threadIdx.x;
    for (int i = t; i < HID * C_OUT; i += 128) w2s[i] = W2[i];
    if (t < C_OUT) b2s[t] = b2[t];
    __syncthreads();
    int i = blockIdx.x * 128 + t;
    if (i >= N) return;
    float a[HID];
#pragma unroll
    for (int k4 = 0; k4 < 4; k4++) {
        float4 v = *(const float4*)&y2[(size_t)i * HID + 4 * k4];
        a[4 * k4 + 0] = v.x; a[4 * k4 + 1] = v.y;
        a[4 * k4 + 2] = v.z; a[4 * k4 + 3] = v.w;
    }
    float o[C_OUT];
#pragma unroll
    for (int j = 0; j < C_OUT; j++) o[j] = b2s[j];
#pragma unroll
    for (int k = 0; k < HID; k++) {
        float av = a[k];
#pragma unroll
        for (int j = 0; j < C_OUT; j++) o[j] += av * w2s[k * C_OUT + j];
    }
#pragma unroll
    for (int jg = 0; jg < C_OUT / 4; jg++) {
        float4 v = make_float4(o[4 * jg + 0], o[4 * jg + 1], o[4 * jg + 2], o[4 * jg + 3]);
        *(float4*)&out[(size_t)i * C_OUT + 4 * jg] = v;
    }
}

// ---------------- launcher ----------------
extern "C" void kernel_launch(void* const* d_in, const int* in_sizes, int n_in,
                              void* d_out, int out_size) {
    const float* x  = (const float*)d_in[0];
    const int*   ei = (const int*)d_in[1];
    const float* W1 = (const float*)d_in[2];
    const float* b1 = (const float*)d_in[3];
    const float* W2 = (const float*)d_in[4];
    const float* b2 = (const float*)d_in[5];
    float* out = (float*)d_out;

    const int N = in_sizes[0] / F_IN;
    const int E = in_sizes[1] / 2;
    const int* src = ei;
    const int* dst = ei + E;

    void *p_deg, *p_dinv, *p_norm, *p_B1, *p_B2;
    cudaGetSymbolAddress(&p_deg,  g_deg);
    cudaGetSymbolAddress(&p_dinv, g_dinv);
    cudaGetSymbolAddress(&p_norm, g_norm);
    cudaGetSymbolAddress(&p_B1,   g_B1);
    cudaGetSymbolAddress(&p_B2,   g_B2);
    int*   deg  = (int*)p_deg;
    float* dinv = (float*)p_dinv;
    float* nrm  = (float*)p_norm;
    float* B1   = (float*)p_B1;
    float* B2   = (float*)p_B2;

    const int TB = 256;
    // 1. degree
    k_zero_deg<<<(N + TB - 1) / TB, TB>>>(deg, N);
    k_hist<<<(E + TB - 1) / TB, TB>>>(dst, deg, E);
    k_dinv<<<(N + TB - 1) / TB, TB>>>(deg, dinv, N);
    // 2. edge norms
    k_norm<<<(E + TB - 1) / TB, TB>>>(src, dst, dinv, nrm, E);
    // 3. h = x @ W1
    k_gemm1<<<(N + 255) / 256, 64>>>(x, W1, B1, N);
    // 4. y1 = A_hat * h  (16-dim aggregation)
    int nv4 = N * (HID / 4);
    k_selfinit<<<(nv4 + TB - 1) / TB, TB>>>((const float4*)B1, dinv, (float4*)B2, N);
    {
        int threads = E * 4;
        k_agg<<<(threads + TB - 1) / TB, TB>>>(src, dst, nrm, (const float4*)B1, (float4*)B2, E);
    }
    // 5. a = relu(y1 + b1)   (B2 -> B1)
    k_relubias<<<(nv4 + TB - 1) / TB, TB>>>((const float4*)B2, b1, (float4*)B1, N);
    // 6. y2 = A_hat * a      (16-dim aggregation; (A a) W2 == A (a W2))
    k_selfinit<<<(nv4 + TB - 1) / TB, TB>>>((const float4*)B1, dinv, (float4*)B2, N);
    {
        int threads = E * 4;
        k_agg<<<(threads + TB - 1) / TB, TB>>>(src, dst, nrm, (const float4*)B1, (float4*)B2, E);
    }
    // 7. out = y2 @ W2 + b2
    k_gemm2<<<(N + 127) / 128, 128>>>(B2, W2, b2, out, N);
}

// round 2
// speedup vs baseline: 1.1126x; 1.1126x over previous
#include <cuda_runtime.h>
#include <cuda_bf16.h>

#define F_IN  512
#define HID   16
#define C_OUT 40
#define MAXN  100000
#define MAXE  3200000

// ---------------- scratch (static device globals, no allocs) ----------------
__device__ __align__(128) int   g_deg [MAXN];
__device__ __align__(128) float g_dinv[MAXN];
__device__ __align__(128) float g_B1  [MAXN * HID];   // h~, later a~
__device__ __align__(128) float g_B2  [MAXN * HID];   // agg accumulators

// ---------------- helpers ----------------
__device__ __forceinline__ void red4(float4* p, float4 v) {
    asm volatile("red.global.add.v4.f32 [%0], {%1,%2,%3,%4};"
                 :: "l"(p), "f"(v.x), "f"(v.y), "f"(v.z), "f"(v.w)
                 : "memory");
}
__device__ __forceinline__ unsigned long long pk2(float lo, float hi) {
    unsigned long long r;
    asm("mov.b64 %0, {%1, %2};" : "=l"(r) : "f"(lo), "f"(hi));
    return r;
}
__device__ __forceinline__ float2 upk2(unsigned long long v) {
    float2 f;
    asm("mov.b64 {%0, %1}, %2;" : "=f"(f.x), "=f"(f.y) : "l"(v));
    return f;
}
__device__ __forceinline__ void fma2(unsigned long long& d, unsigned long long a,
                                     unsigned long long b) {
    asm("fma.rn.f32x2 %0, %1, %2, %0;" : "+l"(d) : "l"(a), "l"(b));
}

// ---------------- kernels ----------------
__global__ void k_zero_deg(int* deg, int N) {
    int i = blockIdx.x * blockDim.x + threadIdx.x;
    if (i < N) deg[i] = 0;
}

__global__ void k_hist(const int* __restrict__ dst, int* deg, int E) {
    int i = blockIdx.x * blockDim.x + threadIdx.x;
    if (i < E) atomicAdd(&deg[dst[i]], 1);
}

__global__ void k_dinv(const int* __restrict__ deg, float* dinv, int N) {
    int i = blockIdx.x * blockDim.x + threadIdx.x;
    if (i < N) dinv[i] = rsqrtf((float)(deg[i] + 1));   // +1 = self-loop
}

// GEMM1: h~[N,16] = dinv[r] * (x[N,512] @ W1[512,16]), written to h0 AND h1.
// 64 threads/block, 256 rows/block (4 rows/thread), k-tiles of 16 staged in smem.
// Inner product uses packed fma.rn.f32x2: row pair (t, t+64) in accA, (t+128, t+192) in accB.
#define G1_PR 257
__global__ __launch_bounds__(64) void k_gemm1(const float* __restrict__ x,
                                              const float* __restrict__ W1,
                                              const float* __restrict__ dinv,
                                              float* __restrict__ h0,
                                              float* __restrict__ h1, int N) {
    __shared__ float  sx[16 * G1_PR];   // [kk][r]
    __shared__ float2 wt2[256];         // [kk][j] duplicated (w,w)
    const int t    = threadIdx.x;
    const int base = blockIdx.x * 256;

    unsigned long long accA[16], accB[16];
#pragma unroll
    for (int j = 0; j < 16; j++) { accA[j] = 0ull; accB[j] = 0ull; }

    for (int kt = 0; kt < F_IN / 16; kt++) {
        __syncthreads();
#pragma unroll
        for (int i = t; i < 256; i += 64) {
            float w = W1[kt * 256 + i];
            wt2[i] = make_float2(w, w);
        }
#pragma unroll
        for (int i = 0; i < 16; i++) {
            int c = t + 64 * i;
            int r = c >> 2, q = c & 3;
            int rg = base + r;
            float4 v = make_float4(0.f, 0.f, 0.f, 0.f);
            if (rg < N)
                v = *(const float4*)&x[(size_t)rg * F_IN + kt * 16 + q * 4];
            sx[(4 * q + 0) * G1_PR + r] = v.x;
            sx[(4 * q + 1) * G1_PR + r] = v.y;
            sx[(4 * q + 2) * G1_PR + r] = v.z;
            sx[(4 * q + 3) * G1_PR + r] = v.w;
        }
        __syncthreads();
        const unsigned long long* wt2u = (const unsigned long long*)wt2;
#pragma unroll
        for (int kk = 0; kk < 16; kk++) {
            unsigned long long xa = pk2(sx[kk * G1_PR + t],       sx[kk * G1_PR + t + 64]);
            unsigned long long xb = pk2(sx[kk * G1_PR + t + 128], sx[kk * G1_PR + t + 192]);
#pragma unroll
            for (int j = 0; j < 16; j++) {
                unsigned long long w = wt2u[kk * 16 + j];
                fma2(accA[j], xa, w);
                fma2(accB[j], xb, w);
            }
        }
    }
    // epilogue: scale by dinv and dual-store
    int r0 = base + t, r1 = base + t + 64, r2 = base + t + 128, r3 = base + t + 192;
    float d0 = (r0 < N) ? dinv[r0] : 0.f;
    float d1 = (r1 < N) ? dinv[r1] : 0.f;
    float d2 = (r2 < N) ? dinv[r2] : 0.f;
    float d3 = (r3 < N) ? dinv[r3] : 0.f;
#pragma unroll
    for (int j4 = 0; j4 < 4; j4++) {
        float2 a0 = upk2(accA[4 * j4 + 0]), a1 = upk2(accA[4 * j4 + 1]);
        float2 a2 = upk2(accA[4 * j4 + 2]), a3 = upk2(accA[4 * j4 + 3]);
        float2 b0 = upk2(accB[4 * j4 + 0]), b1v = upk2(accB[4 * j4 + 1]);
        float2 b2v = upk2(accB[4 * j4 + 2]), b3 = upk2(accB[4 * j4 + 3]);
        if (r0 < N) {
            float4 v = make_float4(a0.x * d0, a1.x * d0, a2.x * d0, a3.x * d0);
            *(float4*)&h0[(size_t)r0 * HID + 4 * j4] = v;
            *(float4*)&h1[(size_t)r0 * HID + 4 * j4] = v;
        }
        if (r1 < N) {
            float4 v = make_float4(a0.y * d1, a1.y * d1, a2.y * d1, a3.y * d1);
            *(float4*)&h0[(size_t)r1 * HID + 4 * j4] = v;
            *(float4*)&h1[(size_t)r1 * HID + 4 * j4] = v;
        }
        if (r2 < N) {
            float4 v = make_float4(b0.x * d2, b1v.x * d2, b2v.x * d2, b3.x * d2);
            *(float4*)&h0[(size_t)r2 * HID + 4 * j4] = v;
            *(float4*)&h1[(size_t)r2 * HID + 4 * j4] = v;
        }
        if (r3 < N) {
            float4 v = make_float4(b0.y * d3, b1v.y * d3, b2v.y * d3, b3.y * d3);
            *(float4*)&h0[(size_t)r3 * HID + 4 * j4] = v;
            *(float4*)&h1[(size_t)r3 * HID + 4 * j4] = v;
        }
    }
}

// edge aggregation: out[dst] += in[src], 4 threads per edge (float4 chunks), no weights
__global__ void k_agg(const int* __restrict__ src, const int* __restrict__ dst,
                      const float4* __restrict__ in4, float4* out4, int E) {
    int tid = blockIdx.x * blockDim.x + threadIdx.x;
    int e = tid >> 2;
    int c = tid & 3;
    if (e < E) {
        int s = src[e];
        int d = dst[e];
        float4 v = in4[s * 4 + c];
        red4(out4 + (size_t)d * 4 + c, v);
    }
}

// a~ = dinv * relu(dinv * y1 + b1), dual-store (layer-2 input + layer-2 agg init)
__global__ void k_relubias(const float4* __restrict__ in4, const float* __restrict__ dinv,
                           const float* __restrict__ b1,
                           float4* __restrict__ o0, float4* __restrict__ o1, int N) {
    int i = blockIdx.x * blockDim.x + threadIdx.x;
    if (i < N * (HID / 4)) {
        float dv = dinv[i >> 2];
        int jb = (i & 3) * 4;
        float4 v = in4[i];
        v.x = fmaxf(fmaf(v.x, dv, b1[jb + 0]), 0.f) * dv;
        v.y = fmaxf(fmaf(v.y, dv, b1[jb + 1]), 0.f) * dv;
        v.z = fmaxf(fmaf(v.z, dv, b1[jb + 2]), 0.f) * dv;
        v.w = fmaxf(fmaf(v.w, dv, b1[jb + 3]), 0.f) * dv;
        o0[i] = v;
        o1[i] = v;
    }
}

// GEMM2 + b2: out[N,40] = (dinv[i] * y2[i,:]) @ W2[16,40] + b2
__global__ __launch_bounds__(128) void k_gemm2(const float* __restrict__ y2,
                                               const float* __restrict__ dinv,
                                               const float* __restrict__ W2,
                                               const float* __restrict__ b2,
                                               float* __restrict__ out, int N) {
    __shared__ float w2s[HID * C_OUT];
    __shared__ float b2s[C_OUT];
    int t = threadIdx.x;
    for (int i = t; i < HID * C_OUT; i += 128) w2s[i] = W2[i];
    if (t < C_OUT) b2s[t] = b2[t];
    __syncthreads();
    int i = blockIdx.x * 128 + t;
    if (i >= N) return;
    float dv = dinv[i];
    float a[HID];
#pragma unroll
    for (int k4 = 0; k4 < 4; k4++) {
        float4 v = *(const float4*)&y2[(size_t)i * HID + 4 * k4];
        a[4 * k4 + 0] = v.x * dv; a[4 * k4 + 1] = v.y * dv;
        a[4 * k4 + 2] = v.z * dv; a[4 * k4 + 3] = v.w * dv;
    }
    float o[C_OUT];
#pragma unroll
    for (int j = 0; j < C_OUT; j++) o[j] = b2s[j];
#pragma unroll
    for (int k = 0; k < HID; k++) {
        float av = a[k];
#pragma unroll
        for (int j = 0; j < C_OUT; j++) o[j] += av * w2s[k * C_OUT + j];
    }
#pragma unroll
    for (int jg = 0; jg < C_OUT / 4; jg++) {
        float4 v = make_float4(o[4 * jg + 0], o[4 * jg + 1], o[4 * jg + 2], o[4 * jg + 3]);
        *(float4*)&out[(size_t)i * C_OUT + 4 * jg] = v;
    }
}

// ---------------- launcher ----------------
extern "C" void kernel_launch(void* const* d_in, const int* in_sizes, int n_in,
                              void* d_out, int out_size) {
    const float* x  = (const float*)d_in[0];
    const int*   ei = (const int*)d_in[1];
    const float* W1 = (const float*)d_in[2];
    const float* b1 = (const float*)d_in[3];
    const float* W2 = (const float*)d_in[4];
    const float* b2 = (const float*)d_in[5];
    float* out = (float*)d_out;

    const int N = in_sizes[0] / F_IN;
    const int E = in_sizes[1] / 2;
    const int* src = ei;
    const int* dst = ei + E;

    void *p_deg, *p_dinv, *p_B1, *p_B2;
    cudaGetSymbolAddress(&p_deg,  g_deg);
    cudaGetSymbolAddress(&p_dinv, g_dinv);
    cudaGetSymbolAddress(&p_B1,   g_B1);
    cudaGetSymbolAddress(&p_B2,   g_B2);
    int*   deg  = (int*)p_deg;
    float* dinv = (float*)p_dinv;
    float* B1   = (float*)p_B1;
    float* B2   = (float*)p_B2;

    const int TB = 256;
    // 1. degree + dinv
    k_zero_deg<<<(N + TB - 1) / TB, TB>>>(deg, N);
    k_hist<<<(E + TB - 1) / TB, TB>>>(dst, deg, E);
    k_dinv<<<(N + TB - 1) / TB, TB>>>(deg, dinv, N);
    // 2. h~ = dinv * (x @ W1)  -> B1 (agg input) and B2 (agg init = self-loop term)
    k_gemm1<<<(N + 255) / 256, 64>>>(x, W1, dinv, B1, B2, N);
    // 3. B2 += A * B1
    {
        int threads = E * 4;
        k_agg<<<(threads + TB - 1) / TB, TB>>>(src, dst, (const float4*)B1, (float4*)B2, E);
    }
    // 4. a~ = dinv * relu(dinv * B2 + b1) -> B1 and B2
    int nv4 = N * (HID / 4);
    k_relubias<<<(nv4 + TB - 1) / TB, TB>>>((const float4*)B2, dinv, b1,
                                            (float4*)B1, (float4*)B2, N);
    // 5. B2 += A * B1
    {
        int threads = E * 4;
        k_agg<<<(threads + TB - 1) / TB, TB>>>(src, dst, (const float4*)B1, (float4*)B2, E);
    }
    // 6. out = (dinv * B2) @ W2 + b2
    k_gemm2<<<(N + 127) / 128, 128>>>(B2, dinv, W2, b2, out, N);
}

// round 3
// speedup vs baseline: 1.1327x; 1.0181x over previous
#include <cuda_runtime.h>
#include <cuda_bf16.h>

#define F_IN  512
#define HID   16
#define C_OUT 40
#define MAXN  100000
#define MAXE  3200000
#define SCAN_BLK 1024          // elements per scan block
#define MAXSB 128              // max scan blocks (100000/1024 = 98)

typedef unsigned long long ull;

// ---------------- scratch (static device globals, no allocs) ----------------
__device__ __align__(128) int   g_deg [MAXN];
__device__ __align__(128) int   g_cnt [MAXN];
__device__ __align__(128) int   g_rp  [MAXN];
__device__ __align__(128) int   g_bsum[MAXSB];
__device__ __align__(128) int   g_csr [MAXE];
__device__ __align__(128) float g_dinv[MAXN];
__device__ __align__(128) float g_B1  [MAXN * HID];
__device__ __align__(128) float g_B2  [MAXN * HID];

// ---------------- helpers ----------------
__device__ __forceinline__ void red4(float* p, float a, float b, float c, float d) {
    asm volatile("red.global.add.v4.f32 [%0], {%1,%2,%3,%4};"
                 :: "l"(p), "f"(a), "f"(b), "f"(c), "f"(d) : "memory");
}
__device__ __forceinline__ ull pkdup(float v) {
    ull r;
    asm("mov.b64 %0, {%1, %1};" : "=l"(r) : "f"(v));
    return r;
}
__device__ __forceinline__ float2 upk2(ull v) {
    float2 f;
    asm("mov.b64 {%0, %1}, %2;" : "=f"(f.x), "=f"(f.y) : "l"(v));
    return f;
}
__device__ __forceinline__ void fma2(ull& d, ull a, ull b) {
    asm("fma.rn.f32x2 %0, %1, %2, %0;" : "+l"(d) : "l"(a), "l"(b));
}

// ---------------- small kernels ----------------
__global__ void k_zero2(int* a, int* b, int N) {
    int i = blockIdx.x * blockDim.x + threadIdx.x;
    if (i < N) { a[i] = 0; b[i] = 0; }
}
__global__ void k_zerof(float4* p, int n4) {
    int i = blockIdx.x * blockDim.x + threadIdx.x;
    if (i < n4) p[i] = make_float4(0.f, 0.f, 0.f, 0.f);
}
__global__ void k_hist(const int* __restrict__ dst, int* deg, int E) {
    int i = blockIdx.x * blockDim.x + threadIdx.x;
    if (i < E) atomicAdd(&deg[dst[i]], 1);
}
__global__ void k_dinv(const int* __restrict__ deg, float* dinv, int N) {
    int i = blockIdx.x * blockDim.x + threadIdx.x;
    if (i < N) dinv[i] = rsqrtf((float)(deg[i] + 1));
}

// ---------------- scan (exclusive prefix of deg -> row_ptr) ----------------
__global__ __launch_bounds__(256) void k_scan1(const int* __restrict__ deg,
                                               int* rp, int* bsum, int N) {
    __shared__ int sd[256];
    int t = threadIdx.x;
    int base = blockIdx.x * SCAN_BLK + t * 4;
    int4 v = make_int4(0, 0, 0, 0);
    if (base + 3 < N) v = *(const int4*)&deg[base];
    else {
        if (base + 0 < N) v.x = deg[base + 0];
        if (base + 1 < N) v.y = deg[base + 1];
        if (base + 2 < N) v.z = deg[base + 2];
    }
    int s = v.x + v.y + v.z + v.w;
    sd[t] = s;
    __syncthreads();
    for (int off = 1; off < 256; off <<= 1) {
        int val = sd[t];
        int add = (t >= off) ? sd[t - off] : 0;
        __syncthreads();
        sd[t] = val + add;
        __syncthreads();
    }
    int excl = (t == 0) ? 0 : sd[t - 1];
    if (t == 255) bsum[blockIdx.x] = sd[255];
    if (base + 0 < N) rp[base + 0] = excl;
    if (base + 1 < N) rp[base + 1] = excl + v.x;
    if (base + 2 < N) rp[base + 2] = excl + v.x + v.y;
    if (base + 3 < N) rp[base + 3] = excl + v.x + v.y + v.z;
}
__global__ __launch_bounds__(MAXSB) void k_scan2(int* bsum, int nb) {
    __shared__ int sd[MAXSB];
    int t = threadIdx.x;
    int v = (t < nb) ? bsum[t] : 0;
    sd[t] = v;
    __syncthreads();
    for (int off = 1; off < MAXSB; off <<= 1) {
        int val = sd[t];
        int add = (t >= off) ? sd[t - off] : 0;
        __syncthreads();
        sd[t] = val + add;
        __syncthreads();
    }
    int excl = (t == 0) ? 0 : sd[t - 1];
    if (t < nb) bsum[t] = excl;
}
__global__ void k_scan3(int* rp, const int* __restrict__ bsum, int N) {
    int i = blockIdx.x * blockDim.x + threadIdx.x;
    if (i < N) rp[i] += bsum[i / SCAN_BLK];
}

// ---------------- CSR fill ----------------
__global__ void k_fill(const int* __restrict__ src, const int* __restrict__ dst,
                       const int* __restrict__ rp, int* cnt, int* csr, int E) {
    int i = blockIdx.x * blockDim.x + threadIdx.x;
    if (i < E) {
        int d = dst[i];
        int pos = rp[d] + atomicAdd(&cnt[d], 1);
        csr[pos] = src[i];
    }
}

// ---------------- GEMM1: h~ = dinv * (x @ W1), K-split red ----------------
// 256 threads, 512 rows/block, 2 rows/thread, K-split over gridDim.y (128 k each).
#define G1_PR 513
__global__ __launch_bounds__(256) void k_gemm1(const float* __restrict__ x,
                                               const float* __restrict__ W1,
                                               const float* __restrict__ dinv,
                                               float* h, int N) {
    __shared__ float sx[16 * G1_PR];   // x tile [kk][row] 16 x 513
    __shared__ ull   wt[16 * 8];       // w tile: 16 kk x 8 u64 (=16 floats)
    const int t    = threadIdx.x;
    const int base = blockIdx.x * 512;
    const int k0   = blockIdx.y * 128;

    ull acc[2][8];
#pragma unroll
    for (int m = 0; m < 2; m++)
#pragma unroll
        for (int j = 0; j < 8; j++) acc[m][j] = 0ull;

    for (int kt = 0; kt < 8; kt++) {
        int kg = k0 + kt * 16;
        __syncthreads();
        if (t < 128) wt[t] = ((const ull*)(W1 + (size_t)kg * 16))[t];
#pragma unroll
        for (int i = 0; i < 8; i++) {
            int c = t + 256 * i;
            int r = c >> 2, q = c & 3;
            int rg = base + r;
            float4 v = make_float4(0.f, 0.f, 0.f, 0.f);
            if (rg < N)
                v = *(const float4*)&x[(size_t)rg * F_IN + kg + q * 4];
            sx[(4 * q + 0) * G1_PR + r] = v.x;
            sx[(4 * q + 1) * G1_PR + r] = v.y;
            sx[(4 * q + 2) * G1_PR + r] = v.z;
            sx[(4 * q + 3) * G1_PR + r] = v.w;
        }
        __syncthreads();
#pragma unroll
        for (int kk = 0; kk < 16; kk++) {
            ull xa = pkdup(sx[kk * G1_PR + t]);
            ull xb = pkdup(sx[kk * G1_PR + t + 256]);
            const ulonglong2* w2 = (const ulonglong2*)&wt[kk * 8];
#pragma unroll
            for (int p = 0; p < 4; p++) {
                ulonglong2 wv = w2[p];
                fma2(acc[0][2 * p + 0], xa, wv.x);
                fma2(acc[0][2 * p + 1], xa, wv.y);
                fma2(acc[1][2 * p + 0], xb, wv.x);
                fma2(acc[1][2 * p + 1], xb, wv.y);
            }
        }
    }
#pragma unroll
    for (int m = 0; m < 2; m++) {
        int rg = base + t + m * 256;
        if (rg < N) {
            float dv = dinv[rg];
            float o[16];
#pragma unroll
            for (int j = 0; j < 8; j++) {
                float2 f = upk2(acc[m][j]);
                o[2 * j + 0] = f.x * dv;
                o[2 * j + 1] = f.y * dv;
            }
#pragma unroll
            for (int j4 = 0; j4 < 4; j4++)
                red4(&h[(size_t)rg * HID + 4 * j4],
                     o[4 * j4 + 0], o[4 * j4 + 1], o[4 * j4 + 2], o[4 * j4 + 3]);
        }
    }
}

// ---------------- CSR aggregation: out[d] = in[d] + sum_{s in row d} in[s] ----
__global__ __launch_bounds__(256) void k_agg_csr(const int* __restrict__ rp,
                                                 const int* __restrict__ deg,
                                                 const int* __restrict__ csr,
                                                 const float4* __restrict__ in4,
                                                 float4* __restrict__ out4, int N) {
    int gtid = blockIdx.x * blockDim.x + threadIdx.x;
    int d = gtid >> 5;
    if (d >= N) return;
    int lane = gtid & 31;
    int c = lane & 3;
    int sub = lane >> 2;
    int beg = __ldg(&rp[d]);
    int cnt = __ldg(&deg[d]);
    float4 acc = (sub == 0) ? __ldg(&in4[(size_t)d * 4 + c])
                            : make_float4(0.f, 0.f, 0.f, 0.f);
    for (int i = sub; i < cnt; i += 8) {
        int s = __ldg(&csr[beg + i]);
        float4 v = __ldg(&in4[(size_t)s * 4 + c]);
        acc.x += v.x; acc.y += v.y; acc.z += v.z; acc.w += v.w;
    }
#pragma unroll
    for (int off = 16; off >= 4; off >>= 1) {
        acc.x += __shfl_xor_sync(0xffffffffu, acc.x, off);
        acc.y += __shfl_xor_sync(0xffffffffu, acc.y, off);
        acc.z += __shfl_xor_sync(0xffffffffu, acc.z, off);
        acc.w += __shfl_xor_sync(0xffffffffu, acc.w, off);
    }
    if (sub == 0) out4[(size_t)d * 4 + c] = acc;
}

// ---------------- a~ = dinv * relu(dinv * y1 + b1) ----------------
__global__ void k_relubias(const float4* __restrict__ in4, const float* __restrict__ dinv,
                           const float* __restrict__ b1, float4* __restrict__ o0, int N) {
    int i = blockIdx.x * blockDim.x + threadIdx.x;
    if (i < N * (HID / 4)) {
        float dv = dinv[i >> 2];
        int jb = (i & 3) * 4;
        float4 v = in4[i];
        v.x = fmaxf(fmaf(v.x, dv, b1[jb + 0]), 0.f) * dv;
        v.y = fmaxf(fmaf(v.y, dv, b1[jb + 1]), 0.f) * dv;
        v.z = fmaxf(fmaf(v.z, dv, b1[jb + 2]), 0.f) * dv;
        v.w = fmaxf(fmaf(v.w, dv, b1[jb + 3]), 0.f) * dv;
        o0[i] = v;
    }
}

// ---------------- GEMM2 + b2 ----------------
__global__ __launch_bounds__(128) void k_gemm2(const float* __restrict__ y2,
                                               const float* __restrict__ dinv,
                                               const float* __restrict__ W2,
                                               const float* __restrict__ b2,
                                               float* __restrict__ out, int N) {
    __shared__ float w2s[HID * C_OUT];
    __shared__ float b2s[C_OUT];
    int t = threadIdx.x;
    for (int i = t; i < HID * C_OUT; i += 128) w2s[i] = W2[i];
    if (t < C_OUT) b2s[t] = b2[t];
    __syncthreads();
    int i = blockIdx.x * 128 + t;
    if (i >= N) return;
    float dv = dinv[i];
    float a[HID];
#pragma unroll
    for (int k4 = 0; k4 < 4; k4++) {
        float4 v = *(const float4*)&y2[(size_t)i * HID + 4 * k4];
        a[4 * k4 + 0] = v.x * dv; a[4 * k4 + 1] = v.y * dv;
        a[4 * k4 + 2] = v.z * dv; a[4 * k4 + 3] = v.w * dv;
    }
    float o[C_OUT];
#pragma unroll
    for (int j = 0; j < C_OUT; j++) o[j] = b2s[j];
#pragma unroll
    for (int k = 0; k < HID; k++) {
        float av = a[k];
#pragma unroll
        for (int j = 0; j < C_OUT; j++) o[j] += av * w2s[k * C_OUT + j];
    }
#pragma unroll
    for (int jg = 0; jg < C_OUT / 4; jg++) {
        float4 v = make_float4(o[4 * jg + 0], o[4 * jg + 1], o[4 * jg + 2], o[4 * jg + 3]);
        *(float4*)&out[(size_t)i * C_OUT + 4 * jg] = v;
    }
}

// ---------------- launcher ----------------
extern "C" void kernel_launch(void* const* d_in, const int* in_sizes, int n_in,
                              void* d_out, int out_size) {
    const float* x  = (const float*)d_in[0];
    const int*   ei = (const int*)d_in[1];
    const float* W1 = (const float*)d_in[2];
    const float* b1 = (const float*)d_in[3];
    const float* W2 = (const float*)d_in[4];
    const float* b2 = (const float*)d_in[5];
    float* out = (float*)d_out;

    const int N = in_sizes[0] / F_IN;
    const int E = in_sizes[1] / 2;
    const int* src = ei;
    const int* dst = ei + E;

    void *p;
    cudaGetSymbolAddress(&p, g_deg);  int*   deg  = (int*)p;
    cudaGetSymbolAddress(&p, g_cnt);  int*   cnt  = (int*)p;
    cudaGetSymbolAddress(&p, g_rp);   int*   rp   = (int*)p;
    cudaGetSymbolAddress(&p, g_bsum); int*   bsum = (int*)p;
    cudaGetSymbolAddress(&p, g_csr);  int*   csr  = (int*)p;
    cudaGetSymbolAddress(&p, g_dinv); float* dinv = (float*)p;
    cudaGetSymbolAddress(&p, g_B1);   float* B1   = (float*)p;
    cudaGetSymbolAddress(&p, g_B2);   float* B2   = (float*)p;

    const int TB = 256;
    const int nv4 = N * (HID / 4);
    const int nb  = (N + SCAN_BLK - 1) / SCAN_BLK;

    // degree + dinv + zero scratch
    k_zero2<<<(N + TB - 1) / TB, TB>>>(deg, cnt, N);
    k_zerof<<<(nv4 + TB - 1) / TB, TB>>>((float4*)B1, nv4);
    k_hist<<<(E + TB - 1) / TB, TB>>>(dst, deg, E);
    k_dinv<<<(N + TB - 1) / TB, TB>>>(deg, dinv, N);
    // CSR build
    k_scan1<<<nb, 256>>>(deg, rp, bsum, N);
    k_scan2<<<1, MAXSB>>>(bsum, nb);
    k_scan3<<<(N + TB - 1) / TB, TB>>>(rp, bsum, N);
    k_fill<<<(E + TB - 1) / TB, TB>>>(src, dst, rp, cnt, csr, E);
    // h~ = dinv * (x @ W1) -> B1 (red-accumulated over 4 K-splits)
    {
        dim3 grid((N + 511) / 512, 4);
        k_gemm1<<<grid, 256>>>(x, W1, dinv, B1, N);
    }
    // B2 = (A+I) * B1
    k_agg_csr<<<(N * 32 + TB - 1) / TB, TB>>>(rp, deg, csr, (const float4*)B1, (float4*)B2, N);
    // B1 = dinv * relu(dinv * B2 + b1)
    k_relubias<<<(nv4 + TB - 1) / TB, TB>>>((const float4*)B2, dinv, b1, (float4*)B1, N);
    // B2 = (A+I) * B1
    k_agg_csr<<<(N * 32 + TB - 1) / TB, TB>>>(rp, deg, csr, (const float4*)B1, (float4*)B2, N);
    // out = (dinv * B2) @ W2 + b2
    k_gemm2<<<(N + 127) / 128, 128>>>(B2, dinv, W2, b2, out, N);
}